// round 1
// baseline (speedup 1.0000x reference)
#include <cuda_runtime.h>
#include <math.h>

// ---------------------------------------------------------------------------
// Problem constants (fixed by the dataset)
//   B=2, Lq=21760, C=256, FD=1024, NH=8, d=32, NL=4, NP=4
// ---------------------------------------------------------------------------
#define MROWS 43520   // B * Lq
#define CDIM  256
#define FDIM  1024

// Scratch (device globals: allocation-free per harness rules)
__device__ float g_q   [MROWS * CDIM];   // src + pos
__device__ float g_val [MROWS * CDIM];   // value projection
__device__ float g_off [MROWS * CDIM];   // sampling offsets (reused for attn proj)
__device__ float g_aw  [MROWS * 128];    // attention weights
__device__ float g_attn[MROWS * CDIM];   // sampled attention output
__device__ float g_x   [MROWS * CDIM];   // after first layernorm
__device__ float g_hid [MROWS * FDIM];   // FFN hidden
__device__ float g_f   [MROWS * CDIM];   // generic 256-wide temp

// ---------------------------------------------------------------------------
// Elementwise: q = src + pos
// ---------------------------------------------------------------------------
__global__ void addq_kernel(const float* __restrict__ a, const float* __restrict__ b,
                            float* __restrict__ o, int n) {
    int i = blockIdx.x * blockDim.x + threadIdx.x;
    if (i < n) o[i] = a[i] + b[i];
}

// ---------------------------------------------------------------------------
// Tiled fp32 GEMM: C[M,N] = A[M,K] @ W[K,N] + bias[N]  (optional ReLU)
// BM=BN=64, BK=16, 256 threads, 4x4 per-thread tile.
// Assumes M%64==0, N%64==0, K%16==0 (true for all calls here).
// ---------------------------------------------------------------------------
template <bool RELU>
__global__ void gemm64_kernel(const float* __restrict__ A, const float* __restrict__ W,
                              const float* __restrict__ bias, float* __restrict__ C,
                              int M, int N, int K) {
    __shared__ __align__(16) float As[16][64];
    __shared__ __align__(16) float Bs[16][64];

    const int tid = threadIdx.x;
    const int tx = tid & 15;          // 0..15 -> col quad
    const int ty = tid >> 4;          // 0..15 -> row quad
    const int row0 = blockIdx.y * 64;
    const int col0 = blockIdx.x * 64;

    // A tile load mapping: each thread loads one float4 (4 consecutive k)
    const int aRow = tid >> 2;             // 0..63
    const int aK   = (tid & 3) * 4;        // 0,4,8,12
    // B tile load mapping: each thread loads one float4 (4 consecutive n)
    const int bK = tid >> 4;               // 0..15
    const int bN = (tid & 15) * 4;         // 0..60

    float acc[4][4];
#pragma unroll
    for (int i = 0; i < 4; i++)
#pragma unroll
        for (int j = 0; j < 4; j++) acc[i][j] = 0.f;

    for (int k0 = 0; k0 < K; k0 += 16) {
        float4 av = *(const float4*)&A[(row0 + aRow) * K + k0 + aK];
        float4 bv = *(const float4*)&W[(k0 + bK) * N + col0 + bN];
        As[aK + 0][aRow] = av.x;
        As[aK + 1][aRow] = av.y;
        As[aK + 2][aRow] = av.z;
        As[aK + 3][aRow] = av.w;
        *(float4*)&Bs[bK][bN] = bv;
        __syncthreads();

#pragma unroll
        for (int kk = 0; kk < 16; kk++) {
            float4 ra = *(const float4*)&As[kk][ty * 4];
            float4 rb = *(const float4*)&Bs[kk][tx * 4];
            float ar[4] = {ra.x, ra.y, ra.z, ra.w};
            float br[4] = {rb.x, rb.y, rb.z, rb.w};
#pragma unroll
            for (int i = 0; i < 4; i++)
#pragma unroll
                for (int j = 0; j < 4; j++) acc[i][j] += ar[i] * br[j];
        }
        __syncthreads();
    }

#pragma unroll
    for (int i = 0; i < 4; i++) {
        int r = row0 + ty * 4 + i;
#pragma unroll
        for (int j = 0; j < 4; j++) {
            int c = col0 + tx * 4 + j;
            float v = acc[i][j] + bias[c];
            if (RELU) v = fmaxf(v, 0.f);
            C[r * N + c] = v;
        }
    }
}

// ---------------------------------------------------------------------------
// Softmax over groups of 16 (per token, per head). One thread per group.
// ---------------------------------------------------------------------------
__global__ void softmax16_kernel(float* __restrict__ aw, int ngroups) {
    int i = blockIdx.x * blockDim.x + threadIdx.x;
    if (i >= ngroups) return;
    float* p = aw + i * 16;
    float m = -1e30f;
#pragma unroll
    for (int k = 0; k < 16; k++) m = fmaxf(m, p[k]);
    float s = 0.f;
    float e[16];
#pragma unroll
    for (int k = 0; k < 16; k++) { e[k] = expf(p[k] - m); s += e[k]; }
    float inv = 1.f / s;
#pragma unroll
    for (int k = 0; k < 16; k++) p[k] = e[k] * inv;
}

// ---------------------------------------------------------------------------
// Deformable sampling. One block per token (256 threads = 8 heads x 32 ch).
// ---------------------------------------------------------------------------
__global__ void sample_kernel(const float* __restrict__ value, const float* __restrict__ off,
                              const float* __restrict__ aw, const float* __restrict__ refp,
                              const int* __restrict__ shapes, const int* __restrict__ lstart,
                              float* __restrict__ outp, int Lq) {
    const int row = blockIdx.x;
    const int t = threadIdx.x;
    const int b = row / Lq;

    __shared__ float s_off[256];
    __shared__ float s_aw[128];
    __shared__ float s_ref[8];
    __shared__ int   s_hw[8];
    __shared__ int   s_st[4];

    s_off[t] = off[row * 256 + t];
    if (t < 128) s_aw[t] = aw[row * 128 + t];
    if (t < 8)   s_ref[t] = refp[row * 8 + t];
    if (t < 8)   s_hw[t] = shapes[t];
    if (t < 4)   s_st[t] = lstart[t];
    __syncthreads();

    const int h = t >> 5;
    const int j = t & 31;
    const int vbase = b * Lq * 256 + h * 32 + j;

    float acc = 0.f;
#pragma unroll
    for (int l = 0; l < 4; l++) {
        const int Hl = s_hw[l * 2], Wl = s_hw[l * 2 + 1];
        const int st = s_st[l];
        const float rx = s_ref[l * 2], ry = s_ref[l * 2 + 1];
        const float fW = (float)Wl, fH = (float)Hl;
#pragma unroll
        for (int p = 0; p < 4; p++) {
            const int oi = (h * 16 + l * 4 + p) * 2;
            const float locx = rx + s_off[oi] / fW;
            const float locy = ry + s_off[oi + 1] / fH;
            const float px = locx * fW - 0.5f;
            const float py = locy * fH - 0.5f;
            const float fx = floorf(px), fy = floorf(py);
            const int x0 = (int)fx, y0 = (int)fy;
            const float wx1 = px - fx, wy1 = py - fy;
            const float wx0 = 1.f - wx1, wy0 = 1.f - wy1;
            const float a = s_aw[h * 16 + l * 4 + p];

#pragma unroll
            for (int dy = 0; dy < 2; dy++) {
                const int yi = y0 + dy;
                if (yi < 0 || yi >= Hl) continue;
                const float wy = dy ? wy1 : wy0;
#pragma unroll
                for (int dx = 0; dx < 2; dx++) {
                    const int xi = x0 + dx;
                    if (xi < 0 || xi >= Wl) continue;
                    const float wx = dx ? wx1 : wx0;
                    acc += a * wx * wy * value[vbase + (st + yi * Wl + xi) * 256];
                }
            }
        }
    }
    outp[row * 256 + t] = acc;
}

// ---------------------------------------------------------------------------
// LayerNorm over C=256 of (A + B). One block (256 threads) per row.
// ---------------------------------------------------------------------------
__global__ void ln_kernel(const float* __restrict__ A, const float* __restrict__ Bt,
                          const float* __restrict__ g, const float* __restrict__ be,
                          float* __restrict__ out) {
    const int row = blockIdx.x;
    const int t = threadIdx.x;
    const float v = A[row * 256 + t] + Bt[row * 256 + t];

    __shared__ float sh[8];
    __shared__ float sh2[8];

    float s = v;
#pragma unroll
    for (int o = 16; o > 0; o >>= 1) s += __shfl_xor_sync(0xffffffffu, s, o);
    if ((t & 31) == 0) sh[t >> 5] = s;
    __syncthreads();
    float mean = 0.f;
#pragma unroll
    for (int i = 0; i < 8; i++) mean += sh[i];
    mean *= (1.f / 256.f);

    const float d = v - mean;
    float s2 = d * d;
#pragma unroll
    for (int o = 16; o > 0; o >>= 1) s2 += __shfl_xor_sync(0xffffffffu, s2, o);
    if ((t & 31) == 0) sh2[t >> 5] = s2;
    __syncthreads();
    float var = 0.f;
#pragma unroll
    for (int i = 0; i < 8; i++) var += sh2[i];
    var *= (1.f / 256.f);

    out[row * 256 + t] = d * rsqrtf(var + 1e-5f) * g[t] + be[t];
}

// ---------------------------------------------------------------------------
// Launch
// ---------------------------------------------------------------------------
extern "C" void kernel_launch(void* const* d_in, const int* in_sizes, int n_in,
                              void* d_out, int out_size) {
    const float* src  = (const float*)d_in[0];
    const float* pos  = (const float*)d_in[1];
    const float* refp = (const float*)d_in[2];
    const int*   shp  = (const int*)d_in[3];
    const int*   lst  = (const int*)d_in[4];
    const float* Wv   = (const float*)d_in[5];
    const float* bv   = (const float*)d_in[6];
    const float* Woff = (const float*)d_in[7];
    const float* boff = (const float*)d_in[8];
    const float* Waw  = (const float*)d_in[9];
    const float* baw  = (const float*)d_in[10];
    const float* Wo   = (const float*)d_in[11];
    const float* bo   = (const float*)d_in[12];
    const float* W1   = (const float*)d_in[13];
    const float* b1   = (const float*)d_in[14];
    const float* W2   = (const float*)d_in[15];
    const float* b2   = (const float*)d_in[16];
    const float* g1   = (const float*)d_in[17];
    const float* be1  = (const float*)d_in[18];
    const float* g2   = (const float*)d_in[19];
    const float* be2  = (const float*)d_in[20];

    const int M = in_sizes[0] / CDIM;   // B*Lq = 43520
    const int Lq = 21760;
    float* out = (float*)d_out;

    float *q, *val, *off, *aw, *attn, *x, *hid, *f;
    cudaGetSymbolAddress((void**)&q,    g_q);
    cudaGetSymbolAddress((void**)&val,  g_val);
    cudaGetSymbolAddress((void**)&off,  g_off);
    cudaGetSymbolAddress((void**)&aw,   g_aw);
    cudaGetSymbolAddress((void**)&attn, g_attn);
    cudaGetSymbolAddress((void**)&x,    g_x);
    cudaGetSymbolAddress((void**)&hid,  g_hid);
    cudaGetSymbolAddress((void**)&f,    g_f);

    const int nElem = M * CDIM;
    addq_kernel<<<(nElem + 255) / 256, 256>>>(src, pos, q, nElem);

    dim3 blk(256);
    // value = src @ Wv + bv
    gemm64_kernel<false><<<dim3(CDIM / 64, M / 64), blk>>>(src, Wv, bv, val, M, CDIM, CDIM);
    // off = q @ Woff + boff
    gemm64_kernel<false><<<dim3(CDIM / 64, M / 64), blk>>>(q, Woff, boff, off, M, CDIM, CDIM);
    // aw logits = q @ Waw + baw
    gemm64_kernel<false><<<dim3(128 / 64, M / 64), blk>>>(q, Waw, baw, aw, M, 128, CDIM);
    // softmax per (token, head)
    softmax16_kernel<<<(M * 8 + 255) / 256, 256>>>(aw, M * 8);
    // deformable sampling
    sample_kernel<<<M, 256>>>(val, off, aw, refp, shp, lst, attn, Lq);
    // attn projection: f = attn @ Wo + bo
    gemm64_kernel<false><<<dim3(CDIM / 64, M / 64), blk>>>(attn, Wo, bo, f, M, CDIM, CDIM);
    // x = ln(src + f)
    ln_kernel<<<M, 256>>>(src, f, g1, be1, x);
    // hid = relu(x @ W1 + b1)
    gemm64_kernel<true><<<dim3(FDIM / 64, M / 64), blk>>>(x, W1, b1, hid, M, FDIM, CDIM);
    // f = hid @ W2 + b2
    gemm64_kernel<false><<<dim3(CDIM / 64, M / 64), blk>>>(hid, W2, b2, f, M, CDIM, FDIM);
    // out = ln(x + f)
    ln_kernel<<<M, 256>>>(x, f, g2, be2, out);
}

// round 2
// speedup vs baseline: 1.3215x; 1.3215x over previous
#include <cuda_runtime.h>
#include <math.h>

// ---------------------------------------------------------------------------
// Problem constants: B=2, Lq=21760, C=256, FD=1024, NH=8, d=32, NL=4, NP=4
// ---------------------------------------------------------------------------
#define MROWS 43520   // B * Lq
#define CDIM  256
#define FDIM  1024

// Scratch (device globals: allocation-free per harness rules)
__device__ float g_q   [MROWS * CDIM];
__device__ float g_val [MROWS * CDIM];
__device__ float g_off [MROWS * CDIM];
__device__ float g_aw  [MROWS * 128];
__device__ float g_attn[MROWS * CDIM];
__device__ float g_x   [MROWS * CDIM];
__device__ float g_hid [MROWS * FDIM];
__device__ float g_f   [MROWS * CDIM];

// ---------------------------------------------------------------------------
// q = src + pos
// ---------------------------------------------------------------------------
__global__ void addq_kernel(const float* __restrict__ a, const float* __restrict__ b,
                            float* __restrict__ o, int n) {
    int i = blockIdx.x * blockDim.x + threadIdx.x;
    if (i < n) o[i] = a[i] + b[i];
}

// ---------------------------------------------------------------------------
// SGEMM: C[M,N] = A[M,K] @ W[K,N] + bias[N], optional ReLU.
// BM=BN=128, BK=16, 256 threads, 8x8 per-thread tile, register-prefetch
// double buffering. Requires M%128==0, N%128==0, K%16==0.
// ---------------------------------------------------------------------------
#define SPAD 132   // padded row stride (floats); 132*4B = 528B, 16B-aligned

template <bool RELU>
__global__ __launch_bounds__(256, 2)
void gemm128_kernel(const float* __restrict__ A, const float* __restrict__ W,
                    const float* __restrict__ bias, float* __restrict__ C,
                    int M, int N, int K) {
    __shared__ __align__(16) float As[16][SPAD];   // [k][m]
    __shared__ __align__(16) float Bs[16][SPAD];   // [k][n]

    const int tid  = threadIdx.x;
    const int tx   = tid & 15;          // 0..15
    const int ty   = tid >> 4;          // 0..15
    const int row0 = blockIdx.y * 128;
    const int col0 = blockIdx.x * 128;

    // A-tile load slots: s in {tid, tid+256}; row = s>>2 (0..127), kq = s&3
    const int aRow0 = tid >> 2;
    const int aKq0  = (tid & 3) * 4;
    const int aRow1 = (tid + 256) >> 2;
    const int aKq1  = ((tid + 256) & 3) * 4;
    // B-tile load slots: s in {tid, tid+256}; k = s>>5 (0..15), n4 = s&31
    const int bK0 = tid >> 5;
    const int bN0 = (tid & 31) * 4;
    const int bK1 = (tid + 256) >> 5;
    const int bN1 = ((tid + 256) & 31) * 4;

    const float* Arow0p = A + (long)(row0 + aRow0) * K + aKq0;
    const float* Arow1p = A + (long)(row0 + aRow1) * K + aKq1;
    const float* Bk0p   = W + (long)bK0 * N + col0 + bN0;
    const float* Bk1p   = W + (long)bK1 * N + col0 + bN1;

    float acc[8][8];
#pragma unroll
    for (int i = 0; i < 8; i++)
#pragma unroll
        for (int j = 0; j < 8; j++) acc[i][j] = 0.f;

    // ---- preload stage 0 ----
    float4 pa0 = *(const float4*)(Arow0p);
    float4 pa1 = *(const float4*)(Arow1p);
    float4 pb0 = *(const float4*)(Bk0p);
    float4 pb1 = *(const float4*)(Bk1p);

    // scatter-store A (transposed), vector-store B
    As[aKq0 + 0][aRow0] = pa0.x;  As[aKq0 + 1][aRow0] = pa0.y;
    As[aKq0 + 2][aRow0] = pa0.z;  As[aKq0 + 3][aRow0] = pa0.w;
    As[aKq1 + 0][aRow1] = pa1.x;  As[aKq1 + 1][aRow1] = pa1.y;
    As[aKq1 + 2][aRow1] = pa1.z;  As[aKq1 + 3][aRow1] = pa1.w;
    *(float4*)&Bs[bK0][bN0] = pb0;
    *(float4*)&Bs[bK1][bN1] = pb1;
    __syncthreads();

    for (int k0 = 0; k0 < K; k0 += 16) {
        const bool hasNext = (k0 + 16) < K;
        if (hasNext) {
            pa0 = *(const float4*)(Arow0p + k0 + 16);
            pa1 = *(const float4*)(Arow1p + k0 + 16);
            pb0 = *(const float4*)(Bk0p + (long)(k0 + 16) * N);
            pb1 = *(const float4*)(Bk1p + (long)(k0 + 16) * N);
        }

#pragma unroll
        for (int kk = 0; kk < 16; kk++) {
            float4 ra0 = *(const float4*)&As[kk][ty * 4];
            float4 ra1 = *(const float4*)&As[kk][64 + ty * 4];
            float4 rb0 = *(const float4*)&Bs[kk][tx * 4];
            float4 rb1 = *(const float4*)&Bs[kk][64 + tx * 4];
            float ar[8] = {ra0.x, ra0.y, ra0.z, ra0.w, ra1.x, ra1.y, ra1.z, ra1.w};
            float br[8] = {rb0.x, rb0.y, rb0.z, rb0.w, rb1.x, rb1.y, rb1.z, rb1.w};
#pragma unroll
            for (int i = 0; i < 8; i++)
#pragma unroll
                for (int j = 0; j < 8; j++) acc[i][j] += ar[i] * br[j];
        }

        if (hasNext) {
            __syncthreads();
            As[aKq0 + 0][aRow0] = pa0.x;  As[aKq0 + 1][aRow0] = pa0.y;
            As[aKq0 + 2][aRow0] = pa0.z;  As[aKq0 + 3][aRow0] = pa0.w;
            As[aKq1 + 0][aRow1] = pa1.x;  As[aKq1 + 1][aRow1] = pa1.y;
            As[aKq1 + 2][aRow1] = pa1.z;  As[aKq1 + 3][aRow1] = pa1.w;
            *(float4*)&Bs[bK0][bN0] = pb0;
            *(float4*)&Bs[bK1][bN1] = pb1;
            __syncthreads();
        }
    }

    // ---- epilogue: bias (+ ReLU), float4 stores ----
    const int c0 = col0 + tx * 4;
    const int c1 = col0 + 64 + tx * 4;
    float4 bias0 = *(const float4*)&bias[c0];
    float4 bias1 = *(const float4*)&bias[c1];

#pragma unroll
    for (int i = 0; i < 8; i++) {
        const int r = row0 + ((i < 4) ? (ty * 4 + i) : (64 + ty * 4 + i - 4));
        float4 v0, v1;
        v0.x = acc[i][0] + bias0.x;  v0.y = acc[i][1] + bias0.y;
        v0.z = acc[i][2] + bias0.z;  v0.w = acc[i][3] + bias0.w;
        v1.x = acc[i][4] + bias1.x;  v1.y = acc[i][5] + bias1.y;
        v1.z = acc[i][6] + bias1.z;  v1.w = acc[i][7] + bias1.w;
        if (RELU) {
            v0.x = fmaxf(v0.x, 0.f); v0.y = fmaxf(v0.y, 0.f);
            v0.z = fmaxf(v0.z, 0.f); v0.w = fmaxf(v0.w, 0.f);
            v1.x = fmaxf(v1.x, 0.f); v1.y = fmaxf(v1.y, 0.f);
            v1.z = fmaxf(v1.z, 0.f); v1.w = fmaxf(v1.w, 0.f);
        }
        *(float4*)&C[(long)r * N + c0] = v0;
        *(float4*)&C[(long)r * N + c1] = v1;
    }
}

// ---------------------------------------------------------------------------
// Softmax over groups of 16 (per token, per head).
// ---------------------------------------------------------------------------
__global__ void softmax16_kernel(float* __restrict__ aw, int ngroups) {
    int i = blockIdx.x * blockDim.x + threadIdx.x;
    if (i >= ngroups) return;
    float* p = aw + i * 16;
    float m = -1e30f;
#pragma unroll
    for (int k = 0; k < 16; k++) m = fmaxf(m, p[k]);
    float s = 0.f;
    float e[16];
#pragma unroll
    for (int k = 0; k < 16; k++) { e[k] = expf(p[k] - m); s += e[k]; }
    float inv = 1.f / s;
#pragma unroll
    for (int k = 0; k < 16; k++) p[k] = e[k] * inv;
}

// ---------------------------------------------------------------------------
// Deformable sampling. One block per token (256 threads = 8 heads x 32 ch).
// ---------------------------------------------------------------------------
__global__ void sample_kernel(const float* __restrict__ value, const float* __restrict__ off,
                              const float* __restrict__ aw, const float* __restrict__ refp,
                              const int* __restrict__ shapes, const int* __restrict__ lstart,
                              float* __restrict__ outp, int Lq) {
    const int row = blockIdx.x;
    const int t = threadIdx.x;
    const int b = row / Lq;

    __shared__ float s_off[256];
    __shared__ float s_aw[128];
    __shared__ float s_ref[8];
    __shared__ int   s_hw[8];
    __shared__ int   s_st[4];

    s_off[t] = off[row * 256 + t];
    if (t < 128) s_aw[t] = aw[row * 128 + t];
    if (t < 8)   s_ref[t] = refp[row * 8 + t];
    if (t < 8)   s_hw[t] = shapes[t];
    if (t < 4)   s_st[t] = lstart[t];
    __syncthreads();

    const int h = t >> 5;
    const int j = t & 31;
    const int vbase = b * Lq * 256 + h * 32 + j;

    float acc = 0.f;
#pragma unroll
    for (int l = 0; l < 4; l++) {
        const int Hl = s_hw[l * 2], Wl = s_hw[l * 2 + 1];
        const int st = s_st[l];
        const float rx = s_ref[l * 2], ry = s_ref[l * 2 + 1];
        const float fW = (float)Wl, fH = (float)Hl;
#pragma unroll
        for (int p = 0; p < 4; p++) {
            const int oi = (h * 16 + l * 4 + p) * 2;
            const float locx = rx + s_off[oi] / fW;
            const float locy = ry + s_off[oi + 1] / fH;
            const float px = locx * fW - 0.5f;
            const float py = locy * fH - 0.5f;
            const float fx = floorf(px), fy = floorf(py);
            const int x0 = (int)fx, y0 = (int)fy;
            const float wx1 = px - fx, wy1 = py - fy;
            const float wx0 = 1.f - wx1, wy0 = 1.f - wy1;
            const float a = s_aw[h * 16 + l * 4 + p];

#pragma unroll
            for (int dy = 0; dy < 2; dy++) {
                const int yi = y0 + dy;
                if (yi < 0 || yi >= Hl) continue;
                const float wy = dy ? wy1 : wy0;
#pragma unroll
                for (int dx = 0; dx < 2; dx++) {
                    const int xi = x0 + dx;
                    if (xi < 0 || xi >= Wl) continue;
                    const float wx = dx ? wx1 : wx0;
                    acc += a * wx * wy * value[vbase + (st + yi * Wl + xi) * 256];
                }
            }
        }
    }
    outp[row * 256 + t] = acc;
}

// ---------------------------------------------------------------------------
// LayerNorm over C=256 of (A + B). One block (256 threads) per row.
// ---------------------------------------------------------------------------
__global__ void ln_kernel(const float* __restrict__ A, const float* __restrict__ Bt,
                          const float* __restrict__ g, const float* __restrict__ be,
                          float* __restrict__ out) {
    const int row = blockIdx.x;
    const int t = threadIdx.x;
    const float v = A[row * 256 + t] + Bt[row * 256 + t];

    __shared__ float sh[8];
    __shared__ float sh2[8];

    float s = v;
#pragma unroll
    for (int o = 16; o > 0; o >>= 1) s += __shfl_xor_sync(0xffffffffu, s, o);
    if ((t & 31) == 0) sh[t >> 5] = s;
    __syncthreads();
    float mean = 0.f;
#pragma unroll
    for (int i = 0; i < 8; i++) mean += sh[i];
    mean *= (1.f / 256.f);

    const float d = v - mean;
    float s2 = d * d;
#pragma unroll
    for (int o = 16; o > 0; o >>= 1) s2 += __shfl_xor_sync(0xffffffffu, s2, o);
    if ((t & 31) == 0) sh2[t >> 5] = s2;
    __syncthreads();
    float var = 0.f;
#pragma unroll
    for (int i = 0; i < 8; i++) var += sh2[i];
    var *= (1.f / 256.f);

    out[row * 256 + t] = d * rsqrtf(var + 1e-5f) * g[t] + be[t];
}

// ---------------------------------------------------------------------------
// Launch
// ---------------------------------------------------------------------------
extern "C" void kernel_launch(void* const* d_in, const int* in_sizes, int n_in,
                              void* d_out, int out_size) {
    const float* src  = (const float*)d_in[0];
    const float* pos  = (const float*)d_in[1];
    const float* refp = (const float*)d_in[2];
    const int*   shp  = (const int*)d_in[3];
    const int*   lst  = (const int*)d_in[4];
    const float* Wv   = (const float*)d_in[5];
    const float* bv   = (const float*)d_in[6];
    const float* Woff = (const float*)d_in[7];
    const float* boff = (const float*)d_in[8];
    const float* Waw  = (const float*)d_in[9];
    const float* baw  = (const float*)d_in[10];
    const float* Wo   = (const float*)d_in[11];
    const float* bo   = (const float*)d_in[12];
    const float* W1   = (const float*)d_in[13];
    const float* b1   = (const float*)d_in[14];
    const float* W2   = (const float*)d_in[15];
    const float* b2   = (const float*)d_in[16];
    const float* g1   = (const float*)d_in[17];
    const float* be1  = (const float*)d_in[18];
    const float* g2   = (const float*)d_in[19];
    const float* be2  = (const float*)d_in[20];

    const int M = in_sizes[0] / CDIM;   // 43520
    const int Lq = 21760;
    float* out = (float*)d_out;

    float *q, *val, *off, *aw, *attn, *x, *hid, *f;
    cudaGetSymbolAddress((void**)&q,    g_q);
    cudaGetSymbolAddress((void**)&val,  g_val);
    cudaGetSymbolAddress((void**)&off,  g_off);
    cudaGetSymbolAddress((void**)&aw,   g_aw);
    cudaGetSymbolAddress((void**)&attn, g_attn);
    cudaGetSymbolAddress((void**)&x,    g_x);
    cudaGetSymbolAddress((void**)&hid,  g_hid);
    cudaGetSymbolAddress((void**)&f,    g_f);

    const int nElem = M * CDIM;
    addq_kernel<<<(nElem + 255) / 256, 256>>>(src, pos, q, nElem);

    dim3 blk(256);
    gemm128_kernel<false><<<dim3(CDIM / 128, M / 128), blk>>>(src, Wv, bv, val, M, CDIM, CDIM);
    gemm128_kernel<false><<<dim3(CDIM / 128, M / 128), blk>>>(q, Woff, boff, off, M, CDIM, CDIM);
    gemm128_kernel<false><<<dim3(128 / 128, M / 128), blk>>>(q, Waw, baw, aw, M, 128, CDIM);
    softmax16_kernel<<<(M * 8 + 255) / 256, 256>>>(aw, M * 8);
    sample_kernel<<<M, 256>>>(val, off, aw, refp, shp, lst, attn, Lq);
    gemm128_kernel<false><<<dim3(CDIM / 128, M / 128), blk>>>(attn, Wo, bo, f, M, CDIM, CDIM);
    ln_kernel<<<M, 256>>>(src, f, g1, be1, x);
    gemm128_kernel<true><<<dim3(FDIM / 128, M / 128), blk>>>(x, W1, b1, hid, M, FDIM, CDIM);
    gemm128_kernel<false><<<dim3(CDIM / 128, M / 128), blk>>>(hid, W2, b2, f, M, CDIM, FDIM);
    ln_kernel<<<M, 256>>>(x, f, g2, be2, out);
}

// round 4
// speedup vs baseline: 2.0261x; 1.5332x over previous
#include <cuda_runtime.h>
#include <cstdint>
#include <math.h>

// ---------------------------------------------------------------------------
// Problem constants: B=2, Lq=21760, C=256, FD=1024, NH=8, d=32, NL=4, NP=4
// ---------------------------------------------------------------------------
#define MROWS 43520
#define CDIM  256
#define FDIM  1024

// Scratch (device globals: allocation-free per harness rules)
__device__ float g_q   [MROWS * CDIM];
__device__ float g_val [MROWS * CDIM];
__device__ float g_off [MROWS * CDIM];
__device__ float g_aw  [MROWS * 128];
__device__ float g_attn[MROWS * CDIM];
__device__ float g_x   [MROWS * CDIM];
__device__ float g_hid [MROWS * FDIM];
__device__ float g_f   [MROWS * CDIM];
// transposed weights [N][K]
__device__ float g_wt  [3 * 65536 + 32768 + 2 * 262144];

#define WT_WV   0
#define WT_WOFF 65536
#define WT_WAW  131072
#define WT_WO   163840
#define WT_W1   229376
#define WT_W2   491520

// ---------------------------------------------------------------------------
// tf32 helpers (baseline PTX, legal on compute_103 family-generic target)
// ---------------------------------------------------------------------------
__device__ __forceinline__ uint32_t f2tf32(float v) {
    uint32_t o;
    asm("cvt.rna.tf32.f32 %0, %1;" : "=r"(o) : "f"(v));
    return o;
}

__device__ __forceinline__ void mma_tf32(float* d, const uint32_t* a, uint32_t b0, uint32_t b1) {
    asm volatile(
        "mma.sync.aligned.m16n8k8.row.col.f32.tf32.tf32.f32 "
        "{%0,%1,%2,%3}, {%4,%5,%6,%7}, {%8,%9}, {%0,%1,%2,%3};"
        : "+f"(d[0]), "+f"(d[1]), "+f"(d[2]), "+f"(d[3])
        : "r"(a[0]), "r"(a[1]), "r"(a[2]), "r"(a[3]), "r"(b0), "r"(b1));
}

// ---------------------------------------------------------------------------
// Weight transpose: Wt[n*K+k] = W[k*N+n]
// ---------------------------------------------------------------------------
__global__ void transpose_kernel(const float* __restrict__ W, float* __restrict__ Wt, int K, int N) {
    __shared__ float t[32][33];
    const int n0 = blockIdx.x * 32, k0 = blockIdx.y * 32;
    const int tx = threadIdx.x, ty = threadIdx.y;
    for (int r = ty; r < 32; r += 8) t[r][tx] = W[(long)(k0 + r) * N + n0 + tx];
    __syncthreads();
    for (int r = ty; r < 32; r += 8) Wt[(long)(n0 + r) * K + k0 + tx] = t[tx][r];
}

// ---------------------------------------------------------------------------
// Tensor-core tf32 GEMM: C[M,N] = A[M,K] @ Bt[N,K]^T + bias, optional ReLU.
// BM=BN=128, BK=32, 256 threads (8 warps, 4x2), warp tile 32x64.
// Smem pitch 36 floats -> bank = (4*row + k) % 32, conflict-free fragments.
// Requires M%128==0, N%128==0, K%32==0.
// ---------------------------------------------------------------------------
#define GPITCH 36

template <bool RELU>
__global__ __launch_bounds__(256, 2)
void gemm_mma_kernel(const float* __restrict__ A, const float* __restrict__ Bt,
                     const float* __restrict__ bias, float* __restrict__ C,
                     int M, int N, int K) {
    __shared__ uint32_t As[128 * GPITCH];
    __shared__ uint32_t Bs[128 * GPITCH];

    const int tid = threadIdx.x;
    const int wid = tid >> 5;
    const int lid = tid & 31;
    const int row0 = blockIdx.y * 128;
    const int col0 = blockIdx.x * 128;
    const int wm = (wid & 3) * 32;   // warp row offset
    const int wn = (wid >> 2) * 64;  // warp col offset
    const int r = lid >> 2;          // 0..7
    const int c = lid & 3;           // 0..3

    // global->smem mapping: 4 float4 per thread per tile
    const int rbase = tid >> 3;          // 0..31; rows rbase + 32*j
    const int kq    = (tid & 7) * 4;     // 0,4,...,28
    const float* Ap = A  + (long)(row0 + rbase) * K + kq;
    const float* Bp = Bt + (long)(col0 + rbase) * K + kq;
    const long str = (long)32 * K;

    float acc[2][8][4];
#pragma unroll
    for (int mt = 0; mt < 2; mt++)
#pragma unroll
        for (int nt = 0; nt < 8; nt++)
#pragma unroll
            for (int e = 0; e < 4; e++) acc[mt][nt][e] = 0.f;

    const int nk = K >> 5;

    // preload chunk 0
    {
#pragma unroll
        for (int j = 0; j < 4; j++) {
            float4 va = *(const float4*)(Ap + j * str);
            float4 vb = *(const float4*)(Bp + j * str);
            uint4 ua = make_uint4(f2tf32(va.x), f2tf32(va.y), f2tf32(va.z), f2tf32(va.w));
            uint4 ub = make_uint4(f2tf32(vb.x), f2tf32(vb.y), f2tf32(vb.z), f2tf32(vb.w));
            *(uint4*)&As[(rbase + 32 * j) * GPITCH + kq] = ua;
            *(uint4*)&Bs[(rbase + 32 * j) * GPITCH + kq] = ub;
        }
    }
    __syncthreads();

    for (int i = 0; i < nk; i++) {
        const bool more = (i + 1) < nk;
        float4 pa[4], pb[4];
        if (more) {
            const int ko = (i + 1) * 32;
#pragma unroll
            for (int j = 0; j < 4; j++) {
                pa[j] = *(const float4*)(Ap + j * str + ko);
                pb[j] = *(const float4*)(Bp + j * str + ko);
            }
        }

#pragma unroll
        for (int ks = 0; ks < 4; ks++) {
            const int kb = ks * 8;
            uint32_t a[2][4];
#pragma unroll
            for (int mt = 0; mt < 2; mt++) {
                const int mb = wm + mt * 16;
                a[mt][0] = As[(mb + r) * GPITCH + kb + c];
                a[mt][1] = As[(mb + r + 8) * GPITCH + kb + c];
                a[mt][2] = As[(mb + r) * GPITCH + kb + c + 4];
                a[mt][3] = As[(mb + r + 8) * GPITCH + kb + c + 4];
            }
#pragma unroll
            for (int nt = 0; nt < 8; nt++) {
                const int nb = (wn + nt * 8 + r) * GPITCH + kb + c;
                const uint32_t b0 = Bs[nb];
                const uint32_t b1 = Bs[nb + 4];
                mma_tf32(acc[0][nt], a[0], b0, b1);
                mma_tf32(acc[1][nt], a[1], b0, b1);
            }
        }

        if (more) {
            __syncthreads();
#pragma unroll
            for (int j = 0; j < 4; j++) {
                uint4 ua = make_uint4(f2tf32(pa[j].x), f2tf32(pa[j].y), f2tf32(pa[j].z), f2tf32(pa[j].w));
                uint4 ub = make_uint4(f2tf32(pb[j].x), f2tf32(pb[j].y), f2tf32(pb[j].z), f2tf32(pb[j].w));
                *(uint4*)&As[(rbase + 32 * j) * GPITCH + kq] = ua;
                *(uint4*)&Bs[(rbase + 32 * j) * GPITCH + kq] = ub;
            }
            __syncthreads();
        }
    }

    // epilogue: per m16n8 tile, thread owns (r, 2c), (r, 2c+1), (r+8, 2c), (r+8, 2c+1)
    float2 bias2[8];
#pragma unroll
    for (int nt = 0; nt < 8; nt++)
        bias2[nt] = *(const float2*)&bias[col0 + wn + nt * 8 + 2 * c];

#pragma unroll
    for (int mt = 0; mt < 2; mt++) {
        const long gr0 = row0 + wm + mt * 16 + r;
        const long gr1 = gr0 + 8;
#pragma unroll
        for (int nt = 0; nt < 8; nt++) {
            const int gc = col0 + wn + nt * 8 + 2 * c;
            float2 v0, v1;
            v0.x = acc[mt][nt][0] + bias2[nt].x;
            v0.y = acc[mt][nt][1] + bias2[nt].y;
            v1.x = acc[mt][nt][2] + bias2[nt].x;
            v1.y = acc[mt][nt][3] + bias2[nt].y;
            if (RELU) {
                v0.x = fmaxf(v0.x, 0.f); v0.y = fmaxf(v0.y, 0.f);
                v1.x = fmaxf(v1.x, 0.f); v1.y = fmaxf(v1.y, 0.f);
            }
            *(float2*)&C[gr0 * N + gc] = v0;
            *(float2*)&C[gr1 * N + gc] = v1;
        }
    }
}

// ---------------------------------------------------------------------------
// q = src + pos
// ---------------------------------------------------------------------------
__global__ void addq_kernel(const float* __restrict__ a, const float* __restrict__ b,
                            float* __restrict__ o, int n) {
    int i = blockIdx.x * blockDim.x + threadIdx.x;
    if (i < n) o[i] = a[i] + b[i];
}

// ---------------------------------------------------------------------------
// Softmax over groups of 16
// ---------------------------------------------------------------------------
__global__ void softmax16_kernel(float* __restrict__ aw, int ngroups) {
    int i = blockIdx.x * blockDim.x + threadIdx.x;
    if (i >= ngroups) return;
    float* p = aw + i * 16;
    float m = -1e30f;
#pragma unroll
    for (int k = 0; k < 16; k++) m = fmaxf(m, p[k]);
    float s = 0.f;
    float e[16];
#pragma unroll
    for (int k = 0; k < 16; k++) { e[k] = expf(p[k] - m); s += e[k]; }
    float inv = 1.f / s;
#pragma unroll
    for (int k = 0; k < 16; k++) p[k] = e[k] * inv;
}

// ---------------------------------------------------------------------------
// Deformable sampling
// ---------------------------------------------------------------------------
__global__ void sample_kernel(const float* __restrict__ value, const float* __restrict__ off,
                              const float* __restrict__ aw, const float* __restrict__ refp,
                              const int* __restrict__ shapes, const int* __restrict__ lstart,
                              float* __restrict__ outp, int Lq) {
    const int row = blockIdx.x;
    const int t = threadIdx.x;
    const int b = row / Lq;

    __shared__ float s_off[256];
    __shared__ float s_aw[128];
    __shared__ float s_ref[8];
    __shared__ int   s_hw[8];
    __shared__ int   s_st[4];

    s_off[t] = off[row * 256 + t];
    if (t < 128) s_aw[t] = aw[row * 128 + t];
    if (t < 8)   s_ref[t] = refp[row * 8 + t];
    if (t < 8)   s_hw[t] = shapes[t];
    if (t < 4)   s_st[t] = lstart[t];
    __syncthreads();

    const int h = t >> 5;
    const int j = t & 31;
    const int vbase = b * Lq * 256 + h * 32 + j;

    float acc = 0.f;
#pragma unroll
    for (int l = 0; l < 4; l++) {
        const int Hl = s_hw[l * 2], Wl = s_hw[l * 2 + 1];
        const int st = s_st[l];
        const float rx = s_ref[l * 2], ry = s_ref[l * 2 + 1];
        const float fW = (float)Wl, fH = (float)Hl;
#pragma unroll
        for (int p = 0; p < 4; p++) {
            const int oi = (h * 16 + l * 4 + p) * 2;
            const float px = (rx + s_off[oi] / fW) * fW - 0.5f;
            const float py = (ry + s_off[oi + 1] / fH) * fH - 0.5f;
            const float fx = floorf(px), fy = floorf(py);
            const int x0 = (int)fx, y0 = (int)fy;
            const float wx1 = px - fx, wy1 = py - fy;
            const float wx0 = 1.f - wx1, wy0 = 1.f - wy1;
            const float a = s_aw[h * 16 + l * 4 + p];

#pragma unroll
            for (int dy = 0; dy < 2; dy++) {
                const int yi = y0 + dy;
                if (yi < 0 || yi >= Hl) continue;
                const float wy = dy ? wy1 : wy0;
#pragma unroll
                for (int dx = 0; dx < 2; dx++) {
                    const int xi = x0 + dx;
                    if (xi < 0 || xi >= Wl) continue;
                    const float wx = dx ? wx1 : wx0;
                    acc += a * wx * wy * value[vbase + (st + yi * Wl + xi) * 256];
                }
            }
        }
    }
    outp[row * 256 + t] = acc;
}

// ---------------------------------------------------------------------------
// LayerNorm over C=256 of (A + B)
// ---------------------------------------------------------------------------
__global__ void ln_kernel(const float* __restrict__ A, const float* __restrict__ Bt,
                          const float* __restrict__ g, const float* __restrict__ be,
                          float* __restrict__ out) {
    const int row = blockIdx.x;
    const int t = threadIdx.x;
    const float v = A[row * 256 + t] + Bt[row * 256 + t];

    __shared__ float sh[8];
    __shared__ float sh2[8];

    float s = v;
#pragma unroll
    for (int o = 16; o > 0; o >>= 1) s += __shfl_xor_sync(0xffffffffu, s, o);
    if ((t & 31) == 0) sh[t >> 5] = s;
    __syncthreads();
    float mean = 0.f;
#pragma unroll
    for (int i = 0; i < 8; i++) mean += sh[i];
    mean *= (1.f / 256.f);

    const float d = v - mean;
    float s2 = d * d;
#pragma unroll
    for (int o = 16; o > 0; o >>= 1) s2 += __shfl_xor_sync(0xffffffffu, s2, o);
    if ((t & 31) == 0) sh2[t >> 5] = s2;
    __syncthreads();
    float var = 0.f;
#pragma unroll
    for (int i = 0; i < 8; i++) var += sh2[i];
    var *= (1.f / 256.f);

    out[row * 256 + t] = d * rsqrtf(var + 1e-5f) * g[t] + be[t];
}

// ---------------------------------------------------------------------------
// Launch
// ---------------------------------------------------------------------------
extern "C" void kernel_launch(void* const* d_in, const int* in_sizes, int n_in,
                              void* d_out, int out_size) {
    const float* src  = (const float*)d_in[0];
    const float* pos  = (const float*)d_in[1];
    const float* refp = (const float*)d_in[2];
    const int*   shp  = (const int*)d_in[3];
    const int*   lst  = (const int*)d_in[4];
    const float* Wv   = (const float*)d_in[5];
    const float* bv   = (const float*)d_in[6];
    const float* Woff = (const float*)d_in[7];
    const float* boff = (const float*)d_in[8];
    const float* Waw  = (const float*)d_in[9];
    const float* baw  = (const float*)d_in[10];
    const float* Wo   = (const float*)d_in[11];
    const float* bo   = (const float*)d_in[12];
    const float* W1   = (const float*)d_in[13];
    const float* b1   = (const float*)d_in[14];
    const float* W2   = (const float*)d_in[15];
    const float* b2   = (const float*)d_in[16];
    const float* g1   = (const float*)d_in[17];
    const float* be1  = (const float*)d_in[18];
    const float* g2   = (const float*)d_in[19];
    const float* be2  = (const float*)d_in[20];

    const int M = in_sizes[0] / CDIM;   // 43520
    const int Lq = 21760;
    float* out = (float*)d_out;

    float *q, *val, *off, *aw, *attn, *x, *hid, *f, *wt;
    cudaGetSymbolAddress((void**)&q,    g_q);
    cudaGetSymbolAddress((void**)&val,  g_val);
    cudaGetSymbolAddress((void**)&off,  g_off);
    cudaGetSymbolAddress((void**)&aw,   g_aw);
    cudaGetSymbolAddress((void**)&attn, g_attn);
    cudaGetSymbolAddress((void**)&x,    g_x);
    cudaGetSymbolAddress((void**)&hid,  g_hid);
    cudaGetSymbolAddress((void**)&f,    g_f);
    cudaGetSymbolAddress((void**)&wt,   g_wt);

    // transpose weights to [N][K]
    dim3 tb(32, 8);
    transpose_kernel<<<dim3(CDIM / 32, CDIM / 32), tb>>>(Wv,   wt + WT_WV,   CDIM, CDIM);
    transpose_kernel<<<dim3(CDIM / 32, CDIM / 32), tb>>>(Woff, wt + WT_WOFF, CDIM, CDIM);
    transpose_kernel<<<dim3(128 / 32,  CDIM / 32), tb>>>(Waw,  wt + WT_WAW,  CDIM, 128);
    transpose_kernel<<<dim3(CDIM / 32, CDIM / 32), tb>>>(Wo,   wt + WT_WO,   CDIM, CDIM);
    transpose_kernel<<<dim3(FDIM / 32, CDIM / 32), tb>>>(W1,   wt + WT_W1,   CDIM, FDIM);
    transpose_kernel<<<dim3(CDIM / 32, FDIM / 32), tb>>>(W2,   wt + WT_W2,   FDIM, CDIM);

    const int nElem = M * CDIM;
    addq_kernel<<<(nElem + 255) / 256, 256>>>(src, pos, q, nElem);

    dim3 blk(256);
    gemm_mma_kernel<false><<<dim3(CDIM / 128, M / 128), blk>>>(src, wt + WT_WV,   bv,   val, M, CDIM, CDIM);
    gemm_mma_kernel<false><<<dim3(CDIM / 128, M / 128), blk>>>(q,   wt + WT_WOFF, boff, off, M, CDIM, CDIM);
    gemm_mma_kernel<false><<<dim3(1,          M / 128), blk>>>(q,   wt + WT_WAW,  baw,  aw,  M, 128,  CDIM);
    softmax16_kernel<<<(M * 8 + 255) / 256, 256>>>(aw, M * 8);
    sample_kernel<<<M, 256>>>(val, off, aw, refp, shp, lst, attn, Lq);
    gemm_mma_kernel<false><<<dim3(CDIM / 128, M / 128), blk>>>(attn, wt + WT_WO, bo, f, M, CDIM, CDIM);
    ln_kernel<<<M, 256>>>(src, f, g1, be1, x);
    gemm_mma_kernel<true><<<dim3(FDIM / 128, M / 128), blk>>>(x,   wt + WT_W1, b1, hid, M, FDIM, CDIM);
    gemm_mma_kernel<false><<<dim3(CDIM / 128, M / 128), blk>>>(hid, wt + WT_W2, b2, f,  M, CDIM, FDIM);
    ln_kernel<<<M, 256>>>(x, f, g2, be2, out);
}

// round 7
// speedup vs baseline: 2.2828x; 1.1267x over previous
#include <cuda_runtime.h>
#include <cstdint>
#include <math.h>

// ---------------------------------------------------------------------------
// Problem constants: B=2, Lq=21760, C=256, FD=1024, NH=8, d=32, NL=4, NP=4
// ---------------------------------------------------------------------------
#define MROWS 43520
#define CDIM  256
#define FDIM  1024

// Scratch (device globals)
__device__ float g_q    [MROWS * CDIM];   // rounded q
__device__ float g_srcr [MROWS * CDIM];   // rounded src
__device__ float g_val  [MROWS * CDIM];
__device__ float g_off  [MROWS * CDIM];
__device__ float g_aw   [MROWS * 128];
__device__ float g_attn [MROWS * CDIM];   // rounded
__device__ float g_x    [MROWS * CDIM];
__device__ float g_xr   [MROWS * CDIM];   // rounded
__device__ float g_hid  [MROWS * FDIM];   // rounded
__device__ float g_f    [MROWS * CDIM];
__device__ float g_wt   [3 * 65536 + 32768 + 2 * 262144]; // rounded, [N][K]

#define WT_WV   0
#define WT_WOFF 65536
#define WT_WAW  131072
#define WT_WO   163840
#define WT_W1   229376
#define WT_W2   491520

// ---------------------------------------------------------------------------
// helpers
// ---------------------------------------------------------------------------
__device__ __forceinline__ uint32_t f2tf32(float v) {
    uint32_t o;
    asm("cvt.rna.tf32.f32 %0, %1;" : "=r"(o) : "f"(v));
    return o;
}
__device__ __forceinline__ float rtf(float v) { return __uint_as_float(f2tf32(v)); }

__device__ __forceinline__ void mma_tf32(float* d, const uint32_t* a, uint32_t b0, uint32_t b1) {
    asm volatile(
        "mma.sync.aligned.m16n8k8.row.col.f32.tf32.tf32.f32 "
        "{%0,%1,%2,%3}, {%4,%5,%6,%7}, {%8,%9}, {%0,%1,%2,%3};"
        : "+f"(d[0]), "+f"(d[1]), "+f"(d[2]), "+f"(d[3])
        : "r"(a[0]), "r"(a[1]), "r"(a[2]), "r"(a[3]), "r"(b0), "r"(b1));
}

__device__ __forceinline__ uint32_t smem_u32(const void* p) {
    uint32_t a;
    asm("{ .reg .u64 t; cvta.to.shared.u64 t, %1; cvt.u32.u64 %0, t; }" : "=r"(a) : "l"(p));
    return a;
}
__device__ __forceinline__ void cp16(uint32_t dst, const void* src) {
    asm volatile("cp.async.ca.shared.global [%0], [%1], 16;" :: "r"(dst), "l"(src));
}
#define CP_COMMIT() asm volatile("cp.async.commit_group;" ::: "memory")
#define CP_WAIT1()  asm volatile("cp.async.wait_group 1;" ::: "memory")
#define CP_WAIT0()  asm volatile("cp.async.wait_group 0;" ::: "memory")

// ---------------------------------------------------------------------------
// Weight transpose + tf32 round: Wt[n*K+k] = round(W[k*N+n])
// ---------------------------------------------------------------------------
__global__ void transpose_kernel(const float* __restrict__ W, float* __restrict__ Wt, int K, int N) {
    __shared__ float t[32][33];
    const int n0 = blockIdx.x * 32, k0 = blockIdx.y * 32;
    const int tx = threadIdx.x, ty = threadIdx.y;
    for (int r = ty; r < 32; r += 8) t[r][tx] = W[(long)(k0 + r) * N + n0 + tx];
    __syncthreads();
    for (int r = ty; r < 32; r += 8) Wt[(long)(n0 + r) * K + k0 + tx] = rtf(t[tx][r]);
}

// ---------------------------------------------------------------------------
// Tensor-core tf32 GEMM: C[M,N] = A[M,K] @ Bt[N,K]^T + bias.
// BM=BN=128, BK=32, 128 threads (4 warps, 2x2), warp tile 64x64.
// cp.async 2-stage pipeline. Inputs must already be tf32-rounded fp32.
// Smem pitch 36 u32 -> bank(4r+c) conflict-free fragment loads.
// Requires M%128==0, N%128==0, K%32==0.
// ---------------------------------------------------------------------------
#define GP 36
#define AMAT 4608              // 128*36 u32 per matrix
#define STAGE_U32 (2 * AMAT)   // A + B per stage
#define GSMEM_BYTES (2 * STAGE_U32 * 4)  // 73728

template <bool RELU, bool ROUND>
__global__ __launch_bounds__(128, 2)
void gemm_mma_kernel(const float* __restrict__ A, const float* __restrict__ Bt,
                     const float* __restrict__ bias, float* __restrict__ C,
                     int M, int N, int K) {
    extern __shared__ uint32_t sm[];

    const int tid = threadIdx.x;
    const int wid = tid >> 5;
    const int lid = tid & 31;
    const int row0 = blockIdx.y * 128;
    const int col0 = blockIdx.x * 128;
    const int wm = (wid & 1) * 64;
    const int wn = (wid >> 1) * 64;
    const int r = lid >> 2;          // 0..7
    const int c = lid & 3;           // 0..3

    // copy geometry: 8 slots/matrix, slot s -> row rbase+16s, fixed kq
    const int rbase = tid >> 3;          // 0..15
    const int kq    = (tid & 7) * 4;     // 0..28
    const float* Ag = A  + (long)(row0 + rbase) * K + kq;
    const float* Bg = Bt + (long)(col0 + rbase) * K + kq;
    const uint32_t smBase = smem_u32(sm);

    const int nk = K >> 5;

    float acc[4][8][4];
#pragma unroll
    for (int mt = 0; mt < 4; mt++)
#pragma unroll
        for (int nt = 0; nt < 8; nt++)
#pragma unroll
            for (int e = 0; e < 4; e++) acc[mt][nt][e] = 0.f;

    // prologue: stage 0, chunk 0
    {
        const uint32_t sA = smBase;
        const uint32_t sB = smBase + AMAT * 4;
#pragma unroll
        for (int s = 0; s < 8; s++) {
            const int row = rbase + 16 * s;
            const uint32_t so = (uint32_t)(row * GP + kq) * 4;
            cp16(sA + so, Ag + (long)(16 * s) * K);
            cp16(sB + so, Bg + (long)(16 * s) * K);
        }
        CP_COMMIT();
    }

    for (int i = 0; i < nk; i++) {
        const int cur = i & 1;
        if (i + 1 < nk) {
            const int nxt = cur ^ 1;
            const uint32_t sA = smBase + (uint32_t)nxt * STAGE_U32 * 4;
            const uint32_t sB = sA + AMAT * 4;
            const long ko = (long)(i + 1) * 32;
#pragma unroll
            for (int s = 0; s < 8; s++) {
                const int row = rbase + 16 * s;
                const uint32_t so = (uint32_t)(row * GP + kq) * 4;
                cp16(sA + so, Ag + (long)(16 * s) * K + ko);
                cp16(sB + so, Bg + (long)(16 * s) * K + ko);
            }
            CP_COMMIT();
            CP_WAIT1();
        } else {
            CP_WAIT0();
        }
        __syncthreads();

        const uint32_t* As = sm + cur * STAGE_U32;
        const uint32_t* Bs = As + AMAT;

#pragma unroll
        for (int ks = 0; ks < 4; ks++) {
            const int kb = ks * 8;
            uint32_t a[4][4];
#pragma unroll
            for (int mt = 0; mt < 4; mt++) {
                const int mb = wm + mt * 16;
                a[mt][0] = As[(mb + r) * GP + kb + c];
                a[mt][1] = As[(mb + r + 8) * GP + kb + c];
                a[mt][2] = As[(mb + r) * GP + kb + c + 4];
                a[mt][3] = As[(mb + r + 8) * GP + kb + c + 4];
            }
#pragma unroll
            for (int nt = 0; nt < 8; nt++) {
                const uint32_t* bp = &Bs[(wn + nt * 8 + r) * GP + kb + c];
                const uint32_t b0 = bp[0];
                const uint32_t b1 = bp[4];
#pragma unroll
                for (int mt = 0; mt < 4; mt++)
                    mma_tf32(acc[mt][nt], a[mt], b0, b1);
            }
        }
        __syncthreads();
    }

    // epilogue
    float2 bias2[8];
#pragma unroll
    for (int nt = 0; nt < 8; nt++)
        bias2[nt] = *(const float2*)&bias[col0 + wn + nt * 8 + 2 * c];

#pragma unroll
    for (int mt = 0; mt < 4; mt++) {
        const long gr0 = row0 + wm + mt * 16 + r;
        const long gr1 = gr0 + 8;
#pragma unroll
        for (int nt = 0; nt < 8; nt++) {
            const int gc = col0 + wn + nt * 8 + 2 * c;
            float2 v0, v1;
            v0.x = acc[mt][nt][0] + bias2[nt].x;
            v0.y = acc[mt][nt][1] + bias2[nt].y;
            v1.x = acc[mt][nt][2] + bias2[nt].x;
            v1.y = acc[mt][nt][3] + bias2[nt].y;
            if (RELU) {
                v0.x = fmaxf(v0.x, 0.f); v0.y = fmaxf(v0.y, 0.f);
                v1.x = fmaxf(v1.x, 0.f); v1.y = fmaxf(v1.y, 0.f);
            }
            if (ROUND) {
                v0.x = rtf(v0.x); v0.y = rtf(v0.y);
                v1.x = rtf(v1.x); v1.y = rtf(v1.y);
            }
            *(float2*)&C[gr0 * N + gc] = v0;
            *(float2*)&C[gr1 * N + gc] = v1;
        }
    }
}

// ---------------------------------------------------------------------------
// q = round(src + pos); src_r = round(src)
// ---------------------------------------------------------------------------
__global__ void addq_kernel(const float* __restrict__ a, const float* __restrict__ b,
                            float* __restrict__ q, float* __restrict__ sr, int n) {
    int i = blockIdx.x * blockDim.x + threadIdx.x;
    if (i < n) {
        float s = a[i];
        q[i] = rtf(s + b[i]);
        sr[i] = rtf(s);
    }
}

// ---------------------------------------------------------------------------
// Softmax over groups of 16
// ---------------------------------------------------------------------------
__global__ void softmax16_kernel(float* __restrict__ aw, int ngroups) {
    int i = blockIdx.x * blockDim.x + threadIdx.x;
    if (i >= ngroups) return;
    float* p = aw + i * 16;
    float m = -1e30f;
#pragma unroll
    for (int k = 0; k < 16; k++) m = fmaxf(m, p[k]);
    float s = 0.f;
    float e[16];
#pragma unroll
    for (int k = 0; k < 16; k++) { e[k] = expf(p[k] - m); s += e[k]; }
    float inv = 1.f / s;
#pragma unroll
    for (int k = 0; k < 16; k++) p[k] = e[k] * inv;
}

// ---------------------------------------------------------------------------
// Deformable sampling (output rounded to tf32 for the Wo GEMM)
// ---------------------------------------------------------------------------
__global__ void sample_kernel(const float* __restrict__ value, const float* __restrict__ off,
                              const float* __restrict__ aw, const float* __restrict__ refp,
                              const int* __restrict__ shapes, const int* __restrict__ lstart,
                              float* __restrict__ outp, int Lq) {
    const int row = blockIdx.x;
    const int t = threadIdx.x;
    const int b = row / Lq;

    __shared__ float s_off[256];
    __shared__ float s_aw[128];
    __shared__ float s_ref[8];
    __shared__ int   s_hw[8];
    __shared__ int   s_st[4];

    s_off[t] = off[row * 256 + t];
    if (t < 128) s_aw[t] = aw[row * 128 + t];
    if (t < 8)   s_ref[t] = refp[row * 8 + t];
    if (t < 8)   s_hw[t] = shapes[t];
    if (t < 4)   s_st[t] = lstart[t];
    __syncthreads();

    const int h = t >> 5;
    const int j = t & 31;
    const int vbase = b * Lq * 256 + h * 32 + j;

    float acc = 0.f;
#pragma unroll
    for (int l = 0; l < 4; l++) {
        const int Hl = s_hw[l * 2], Wl = s_hw[l * 2 + 1];
        const int st = s_st[l];
        const float rx = s_ref[l * 2], ry = s_ref[l * 2 + 1];
        const float fW = (float)Wl, fH = (float)Hl;
#pragma unroll
        for (int p = 0; p < 4; p++) {
            const int oi = (h * 16 + l * 4 + p) * 2;
            const float px = (rx + s_off[oi] / fW) * fW - 0.5f;
            const float py = (ry + s_off[oi + 1] / fH) * fH - 0.5f;
            const float fx = floorf(px), fy = floorf(py);
            const int x0 = (int)fx, y0 = (int)fy;
            const float wx1 = px - fx, wy1 = py - fy;
            const float wx0 = 1.f - wx1, wy0 = 1.f - wy1;
            const float a = s_aw[h * 16 + l * 4 + p];

#pragma unroll
            for (int dy = 0; dy < 2; dy++) {
                const int yi = y0 + dy;
                if (yi < 0 || yi >= Hl) continue;
                const float wy = dy ? wy1 : wy0;
#pragma unroll
                for (int dx = 0; dx < 2; dx++) {
                    const int xi = x0 + dx;
                    if (xi < 0 || xi >= Wl) continue;
                    const float wx = dx ? wx1 : wx0;
                    acc += a * wx * wy * value[vbase + (st + yi * Wl + xi) * 256];
                }
            }
        }
    }
    outp[row * 256 + t] = rtf(acc);
}

// ---------------------------------------------------------------------------
// LayerNorm over C=256 of (A + B); optional rounded side copy
// ---------------------------------------------------------------------------
__global__ void ln_kernel(const float* __restrict__ A, const float* __restrict__ Bt,
                          const float* __restrict__ g, const float* __restrict__ be,
                          float* __restrict__ out, float* __restrict__ out_r) {
    const int row = blockIdx.x;
    const int t = threadIdx.x;
    const float v = A[row * 256 + t] + Bt[row * 256 + t];

    __shared__ float sh[8];
    __shared__ float sh2[8];

    float s = v;
#pragma unroll
    for (int o = 16; o > 0; o >>= 1) s += __shfl_xor_sync(0xffffffffu, s, o);
    if ((t & 31) == 0) sh[t >> 5] = s;
    __syncthreads();
    float mean = 0.f;
#pragma unroll
    for (int i = 0; i < 8; i++) mean += sh[i];
    mean *= (1.f / 256.f);

    const float d = v - mean;
    float s2 = d * d;
#pragma unroll
    for (int o = 16; o > 0; o >>= 1) s2 += __shfl_xor_sync(0xffffffffu, s2, o);
    if ((t & 31) == 0) sh2[t >> 5] = s2;
    __syncthreads();
    float var = 0.f;
#pragma unroll
    for (int i = 0; i < 8; i++) var += sh2[i];
    var *= (1.f / 256.f);

    const float o = d * rsqrtf(var + 1e-5f) * g[t] + be[t];
    out[row * 256 + t] = o;
    if (out_r) out_r[row * 256 + t] = rtf(o);
}

// ---------------------------------------------------------------------------
// Launch
// ---------------------------------------------------------------------------
extern "C" void kernel_launch(void* const* d_in, const int* in_sizes, int n_in,
                              void* d_out, int out_size) {
    const float* src  = (const float*)d_in[0];
    const float* pos  = (const float*)d_in[1];
    const float* refp = (const float*)d_in[2];
    const int*   shp  = (const int*)d_in[3];
    const int*   lst  = (const int*)d_in[4];
    const float* Wv   = (const float*)d_in[5];
    const float* bv   = (const float*)d_in[6];
    const float* Woff = (const float*)d_in[7];
    const float* boff = (const float*)d_in[8];
    const float* Waw  = (const float*)d_in[9];
    const float* baw  = (const float*)d_in[10];
    const float* Wo   = (const float*)d_in[11];
    const float* bo   = (const float*)d_in[12];
    const float* W1   = (const float*)d_in[13];
    const float* b1   = (const float*)d_in[14];
    const float* W2   = (const float*)d_in[15];
    const float* b2   = (const float*)d_in[16];
    const float* g1   = (const float*)d_in[17];
    const float* be1  = (const float*)d_in[18];
    const float* g2   = (const float*)d_in[19];
    const float* be2  = (const float*)d_in[20];

    const int M = in_sizes[0] / CDIM;   // 43520
    const int Lq = 21760;
    float* out = (float*)d_out;

    float *q, *srcr, *val, *off, *aw, *attn, *x, *xr, *hid, *f, *wt;
    cudaGetSymbolAddress((void**)&q,    g_q);
    cudaGetSymbolAddress((void**)&srcr, g_srcr);
    cudaGetSymbolAddress((void**)&val,  g_val);
    cudaGetSymbolAddress((void**)&off,  g_off);
    cudaGetSymbolAddress((void**)&aw,   g_aw);
    cudaGetSymbolAddress((void**)&attn, g_attn);
    cudaGetSymbolAddress((void**)&x,    g_x);
    cudaGetSymbolAddress((void**)&xr,   g_xr);
    cudaGetSymbolAddress((void**)&hid,  g_hid);
    cudaGetSymbolAddress((void**)&f,    g_f);
    cudaGetSymbolAddress((void**)&wt,   g_wt);

    // allow 72KB dynamic smem on GEMM variants (idempotent)
    cudaFuncSetAttribute(gemm_mma_kernel<false, false>,
                         cudaFuncAttributeMaxDynamicSharedMemorySize, GSMEM_BYTES);
    cudaFuncSetAttribute(gemm_mma_kernel<true, true>,
                         cudaFuncAttributeMaxDynamicSharedMemorySize, GSMEM_BYTES);

    // transpose + round weights to [N][K]
    dim3 tb(32, 8);
    transpose_kernel<<<dim3(CDIM / 32, CDIM / 32), tb>>>(Wv,   wt + WT_WV,   CDIM, CDIM);
    transpose_kernel<<<dim3(CDIM / 32, CDIM / 32), tb>>>(Woff, wt + WT_WOFF, CDIM, CDIM);
    transpose_kernel<<<dim3(128 / 32,  CDIM / 32), tb>>>(Waw,  wt + WT_WAW,  CDIM, 128);
    transpose_kernel<<<dim3(CDIM / 32, CDIM / 32), tb>>>(Wo,   wt + WT_WO,   CDIM, CDIM);
    transpose_kernel<<<dim3(FDIM / 32, CDIM / 32), tb>>>(W1,   wt + WT_W1,   CDIM, FDIM);
    transpose_kernel<<<dim3(CDIM / 32, FDIM / 32), tb>>>(W2,   wt + WT_W2,   FDIM, CDIM);

    const int nElem = M * CDIM;
    addq_kernel<<<(nElem + 255) / 256, 256>>>(src, pos, q, srcr, nElem);

    dim3 blk(128);
    gemm_mma_kernel<false, false><<<dim3(CDIM / 128, M / 128), blk, GSMEM_BYTES>>>(srcr, wt + WT_WV,   bv,   val, M, CDIM, CDIM);
    gemm_mma_kernel<false, false><<<dim3(CDIM / 128, M / 128), blk, GSMEM_BYTES>>>(q,    wt + WT_WOFF, boff, off, M, CDIM, CDIM);
    gemm_mma_kernel<false, false><<<dim3(1,          M / 128), blk, GSMEM_BYTES>>>(q,    wt + WT_WAW,  baw,  aw,  M, 128,  CDIM);
    softmax16_kernel<<<(M * 8 + 255) / 256, 256>>>(aw, M * 8);
    sample_kernel<<<M, 256>>>(val, off, aw, refp, shp, lst, attn, Lq);
    gemm_mma_kernel<false, false><<<dim3(CDIM / 128, M / 128), blk, GSMEM_BYTES>>>(attn, wt + WT_WO, bo, f, M, CDIM, CDIM);
    ln_kernel<<<M, 256>>>(src, f, g1, be1, x, xr);
    gemm_mma_kernel<true, true><<<dim3(FDIM / 128, M / 128), blk, GSMEM_BYTES>>>(xr,  wt + WT_W1, b1, hid, M, FDIM, CDIM);
    gemm_mma_kernel<false, false><<<dim3(CDIM / 128, M / 128), blk, GSMEM_BYTES>>>(hid, wt + WT_W2, b2, f,  M, CDIM, FDIM);
    ln_kernel<<<M, 256>>>(x, f, g2, be2, out, nullptr);
}

// round 9
// speedup vs baseline: 2.3133x; 1.0134x over previous
#include <cuda_runtime.h>
#include <cstdint>
#include <math.h>

// ---------------------------------------------------------------------------
// Problem constants: B=2, Lq=21760, C=256, FD=1024, NH=8, d=32, NL=4, NP=4
// ---------------------------------------------------------------------------
#define MROWS 43520
#define CDIM  256
#define FDIM  1024

// Scratch (device globals)
__device__ float g_q    [MROWS * CDIM];   // rounded q
__device__ float g_srcr [MROWS * CDIM];   // rounded src
__device__ float g_val  [MROWS * CDIM];
__device__ float g_off  [MROWS * CDIM];
__device__ float g_aw   [MROWS * 128];    // logits (softmax fused into sampler)
__device__ float g_attn [MROWS * CDIM];   // rounded
__device__ float g_x    [MROWS * CDIM];
__device__ float g_xr   [MROWS * CDIM];   // rounded
__device__ float g_hid  [MROWS * FDIM];   // rounded
__device__ float g_f    [MROWS * CDIM];
__device__ float g_wt   [3 * 65536 + 32768 + 2 * 262144]; // rounded, [N][K]

#define WT_WV   0
#define WT_WOFF 65536
#define WT_WAW  131072
#define WT_WO   163840
#define WT_W1   229376
#define WT_W2   491520

// ---------------------------------------------------------------------------
// helpers
// ---------------------------------------------------------------------------
__device__ __forceinline__ uint32_t f2tf32(float v) {
    uint32_t o;
    asm("cvt.rna.tf32.f32 %0, %1;" : "=r"(o) : "f"(v));
    return o;
}
__device__ __forceinline__ float rtf(float v) { return __uint_as_float(f2tf32(v)); }

__device__ __forceinline__ void mma_tf32(float* d, const uint32_t* a, uint32_t b0, uint32_t b1) {
    asm volatile(
        "mma.sync.aligned.m16n8k8.row.col.f32.tf32.tf32.f32 "
        "{%0,%1,%2,%3}, {%4,%5,%6,%7}, {%8,%9}, {%0,%1,%2,%3};"
        : "+f"(d[0]), "+f"(d[1]), "+f"(d[2]), "+f"(d[3])
        : "r"(a[0]), "r"(a[1]), "r"(a[2]), "r"(a[3]), "r"(b0), "r"(b1));
}

__device__ __forceinline__ void ldsm4(uint32_t& r0, uint32_t& r1, uint32_t& r2, uint32_t& r3,
                                      uint32_t addr) {
    asm volatile("ldmatrix.sync.aligned.m8n8.x4.shared.b16 {%0,%1,%2,%3}, [%4];"
                 : "=r"(r0), "=r"(r1), "=r"(r2), "=r"(r3) : "r"(addr));
}

__device__ __forceinline__ uint32_t smem_u32(const void* p) {
    uint32_t a;
    asm("{ .reg .u64 t; cvta.to.shared.u64 t, %1; cvt.u32.u64 %0, t; }" : "=r"(a) : "l"(p));
    return a;
}
__device__ __forceinline__ void cp16(uint32_t dst, const void* src) {
    asm volatile("cp.async.ca.shared.global [%0], [%1], 16;" :: "r"(dst), "l"(src));
}
#define CP_COMMIT() asm volatile("cp.async.commit_group;" ::: "memory")
#define CP_WAIT1()  asm volatile("cp.async.wait_group 1;" ::: "memory")
#define CP_WAIT0()  asm volatile("cp.async.wait_group 0;" ::: "memory")

// ---------------------------------------------------------------------------
// Weight transpose + tf32 round: Wt[n*K+k] = round(W[k*N+n])
// ---------------------------------------------------------------------------
__global__ void transpose_kernel(const float* __restrict__ W, float* __restrict__ Wt, int K, int N) {
    __shared__ float t[32][33];
    const int n0 = blockIdx.x * 32, k0 = blockIdx.y * 32;
    const int tx = threadIdx.x, ty = threadIdx.y;
    for (int r = ty; r < 32; r += 8) t[r][tx] = W[(long)(k0 + r) * N + n0 + tx];
    __syncthreads();
    for (int r = ty; r < 32; r += 8) Wt[(long)(n0 + r) * K + k0 + tx] = rtf(t[tx][r]);
}

// ---------------------------------------------------------------------------
// Tensor-core tf32 GEMM: C[M,N] = A[M,K] @ Bt[N,K]^T + bias.
// BM=BN=128, BK=32, 128 threads (4 warps, 2x2), warp tile 64x64.
// cp.async 2-stage pipeline + ldmatrix fragment loads.
// Smem pitch 36 u32 -> conflict-free LDSM row fetches (4i mod 32 coverage).
// Requires M%128==0, N%128==0, K%32==0. Inputs pre-rounded to tf32.
// ---------------------------------------------------------------------------
#define GP 36
#define AMAT 4608              // 128*36 u32 per matrix
#define STAGE_U32 (2 * AMAT)   // A + B per stage
#define GSMEM_BYTES (2 * STAGE_U32 * 4)  // 73728

template <bool RELU, bool ROUND>
__global__ __launch_bounds__(128, 2)
void gemm_mma_kernel(const float* __restrict__ A, const float* __restrict__ Bt,
                     const float* __restrict__ bias, float* __restrict__ C,
                     int M, int N, int K) {
    extern __shared__ uint32_t sm[];

    const int tid = threadIdx.x;
    const int wid = tid >> 5;
    const int lid = tid & 31;
    const int row0 = blockIdx.y * 128;
    const int col0 = blockIdx.x * 128;
    const int wm = (wid & 1) * 64;
    const int wn = (wid >> 1) * 64;
    const int r = lid >> 2;          // 0..7
    const int c = lid & 3;           // 0..3

    // copy geometry: 8 slots/matrix, slot s -> row rbase+16s, fixed kq
    const int rbase = tid >> 3;          // 0..15
    const int kq    = (tid & 7) * 4;     // 0..28
    const float* Ag = A  + (long)(row0 + rbase) * K + kq;
    const float* Bg = Bt + (long)(col0 + rbase) * K + kq;
    const uint32_t smBase = smem_u32(sm);

    // ldmatrix per-lane word offsets (within stage)
    // A, per mt: row = wm + mt*16 + (lid&15), kcol = 4*(lid>>4)
    uint32_t aoff[4];
#pragma unroll
    for (int mt = 0; mt < 4; mt++)
        aoff[mt] = (uint32_t)((wm + mt * 16 + (lid & 15)) * GP + 4 * (lid >> 4));
    // B, per nt-pair p: row = wn + p*16 + (lid&7) + 8*(lid>>4), kcol = 4*((lid>>3)&1)
    uint32_t boff[4];
#pragma unroll
    for (int p = 0; p < 4; p++)
        boff[p] = (uint32_t)(AMAT + (wn + p * 16 + (lid & 7) + 8 * (lid >> 4)) * GP
                             + 4 * ((lid >> 3) & 1));

    const int nk = K >> 5;

    float acc[4][8][4];
#pragma unroll
    for (int mt = 0; mt < 4; mt++)
#pragma unroll
        for (int nt = 0; nt < 8; nt++)
#pragma unroll
            for (int e = 0; e < 4; e++) acc[mt][nt][e] = 0.f;

    // prologue: stage 0, chunk 0
    {
        const uint32_t sA = smBase;
        const uint32_t sB = smBase + AMAT * 4;
#pragma unroll
        for (int s = 0; s < 8; s++) {
            const int row = rbase + 16 * s;
            const uint32_t so = (uint32_t)(row * GP + kq) * 4;
            cp16(sA + so, Ag + (long)(16 * s) * K);
            cp16(sB + so, Bg + (long)(16 * s) * K);
        }
        CP_COMMIT();
    }

    for (int i = 0; i < nk; i++) {
        const int cur = i & 1;
        if (i + 1 < nk) {
            const int nxt = cur ^ 1;
            const uint32_t sA = smBase + (uint32_t)nxt * STAGE_U32 * 4;
            const uint32_t sB = sA + AMAT * 4;
            const long ko = (long)(i + 1) * 32;
#pragma unroll
            for (int s = 0; s < 8; s++) {
                const int row = rbase + 16 * s;
                const uint32_t so = (uint32_t)(row * GP + kq) * 4;
                cp16(sA + so, Ag + (long)(16 * s) * K + ko);
                cp16(sB + so, Bg + (long)(16 * s) * K + ko);
            }
            CP_COMMIT();
            CP_WAIT1();
        } else {
            CP_WAIT0();
        }
        __syncthreads();

        const uint32_t stageB = smBase + (uint32_t)cur * STAGE_U32 * 4;

#pragma unroll
        for (int ks = 0; ks < 4; ks++) {
            const uint32_t kb4 = (uint32_t)(ks * 8) * 4;
            uint32_t a[4][4];
#pragma unroll
            for (int mt = 0; mt < 4; mt++)
                ldsm4(a[mt][0], a[mt][1], a[mt][2], a[mt][3], stageB + aoff[mt] * 4 + kb4);
            uint32_t b[8][2];
#pragma unroll
            for (int p = 0; p < 4; p++)
                ldsm4(b[2 * p][0], b[2 * p][1], b[2 * p + 1][0], b[2 * p + 1][1],
                      stageB + boff[p] * 4 + kb4);
#pragma unroll
            for (int nt = 0; nt < 8; nt++)
#pragma unroll
                for (int mt = 0; mt < 4; mt++)
                    mma_tf32(acc[mt][nt], a[mt], b[nt][0], b[nt][1]);
        }
        __syncthreads();
    }

    // epilogue
    float2 bias2[8];
#pragma unroll
    for (int nt = 0; nt < 8; nt++)
        bias2[nt] = *(const float2*)&bias[col0 + wn + nt * 8 + 2 * c];

#pragma unroll
    for (int mt = 0; mt < 4; mt++) {
        const long gr0 = row0 + wm + mt * 16 + r;
        const long gr1 = gr0 + 8;
#pragma unroll
        for (int nt = 0; nt < 8; nt++) {
            const int gc = col0 + wn + nt * 8 + 2 * c;
            float2 v0, v1;
            v0.x = acc[mt][nt][0] + bias2[nt].x;
            v0.y = acc[mt][nt][1] + bias2[nt].y;
            v1.x = acc[mt][nt][2] + bias2[nt].x;
            v1.y = acc[mt][nt][3] + bias2[nt].y;
            if (RELU) {
                v0.x = fmaxf(v0.x, 0.f); v0.y = fmaxf(v0.y, 0.f);
                v1.x = fmaxf(v1.x, 0.f); v1.y = fmaxf(v1.y, 0.f);
            }
            if (ROUND) {
                v0.x = rtf(v0.x); v0.y = rtf(v0.y);
                v1.x = rtf(v1.x); v1.y = rtf(v1.y);
            }
            *(float2*)&C[gr0 * N + gc] = v0;
            *(float2*)&C[gr1 * N + gc] = v1;
        }
    }
}

// ---------------------------------------------------------------------------
// q = round(src + pos); src_r = round(src)
// ---------------------------------------------------------------------------
__global__ void addq_kernel(const float* __restrict__ a, const float* __restrict__ b,
                            float* __restrict__ q, float* __restrict__ sr, int n) {
    int i = blockIdx.x * blockDim.x + threadIdx.x;
    if (i < n) {
        float s = a[i];
        q[i] = rtf(s + b[i]);
        sr[i] = rtf(s);
    }
}

// ---------------------------------------------------------------------------
// Deformable sampling with fused softmax (input = logits).
// One block per token (256 threads = 8 heads x 32 ch).
// ---------------------------------------------------------------------------
__global__ void sample_kernel(const float* __restrict__ value, const float* __restrict__ off,
                              const float* __restrict__ awl, const float* __restrict__ refp,
                              const int* __restrict__ shapes, const int* __restrict__ lstart,
                              float* __restrict__ outp, int Lq) {
    const int row = blockIdx.x;
    const int t = threadIdx.x;
    const int b = row / Lq;

    __shared__ float s_off[256];
    __shared__ float s_aw[128];
    __shared__ float s_ref[8];
    __shared__ int   s_hw[8];
    __shared__ int   s_st[4];

    s_off[t] = off[row * 256 + t];
    if (t < 8)   s_ref[t] = refp[row * 8 + t];
    if (t < 8)   s_hw[t] = shapes[t];
    if (t < 4)   s_st[t] = lstart[t];
    // fused softmax over 16-groups: warps 0-3 handle the 128 logits
    if (t < 128) {
        const float v = awl[row * 128 + t];
        float m = v;
#pragma unroll
        for (int o = 8; o > 0; o >>= 1) m = fmaxf(m, __shfl_xor_sync(0xffffffffu, m, o, 16));
        const float e = expf(v - m);
        float s = e;
#pragma unroll
        for (int o = 8; o > 0; o >>= 1) s += __shfl_xor_sync(0xffffffffu, s, o, 16);
        s_aw[t] = e / s;
    }
    __syncthreads();

    const int h = t >> 5;
    const int j = t & 31;
    const int vbase = b * Lq * 256 + h * 32 + j;

    float acc = 0.f;
#pragma unroll
    for (int l = 0; l < 4; l++) {
        const int Hl = s_hw[l * 2], Wl = s_hw[l * 2 + 1];
        const int st = s_st[l];
        const float rx = s_ref[l * 2], ry = s_ref[l * 2 + 1];
        const float fW = (float)Wl, fH = (float)Hl;
#pragma unroll
        for (int p = 0; p < 4; p++) {
            const int oi = (h * 16 + l * 4 + p) * 2;
            const float px = (rx + s_off[oi] / fW) * fW - 0.5f;
            const float py = (ry + s_off[oi + 1] / fH) * fH - 0.5f;
            const float fx = floorf(px), fy = floorf(py);
            const int x0 = (int)fx, y0 = (int)fy;
            const float wx1 = px - fx, wy1 = py - fy;
            const float wx0 = 1.f - wx1, wy0 = 1.f - wy1;
            const float a = s_aw[h * 16 + l * 4 + p];

#pragma unroll
            for (int dy = 0; dy < 2; dy++) {
                const int yi = y0 + dy;
                if (yi < 0 || yi >= Hl) continue;
                const float wy = dy ? wy1 : wy0;
#pragma unroll
                for (int dx = 0; dx < 2; dx++) {
                    const int xi = x0 + dx;
                    if (xi < 0 || xi >= Wl) continue;
                    const float wx = dx ? wx1 : wx0;
                    acc += a * wx * wy * value[vbase + (st + yi * Wl + xi) * 256];
                }
            }
        }
    }
    outp[row * 256 + t] = rtf(acc);
}

// ---------------------------------------------------------------------------
// LayerNorm over C=256 of (A + B); optional rounded side copy
// ---------------------------------------------------------------------------
__global__ void ln_kernel(const float* __restrict__ A, const float* __restrict__ Bt,
                          const float* __restrict__ g, const float* __restrict__ be,
                          float* __restrict__ out, float* __restrict__ out_r) {
    const int row = blockIdx.x;
    const int t = threadIdx.x;
    const float v = A[row * 256 + t] + Bt[row * 256 + t];

    __shared__ float sh[8];
    __shared__ float sh2[8];

    float s = v;
#pragma unroll
    for (int o = 16; o > 0; o >>= 1) s += __shfl_xor_sync(0xffffffffu, s, o);
    if ((t & 31) == 0) sh[t >> 5] = s;
    __syncthreads();
    float mean = 0.f;
#pragma unroll
    for (int i = 0; i < 8; i++) mean += sh[i];
    mean *= (1.f / 256.f);

    const float d = v - mean;
    float s2 = d * d;
#pragma unroll
    for (int o = 16; o > 0; o >>= 1) s2 += __shfl_xor_sync(0xffffffffu, s2, o);
    if ((t & 31) == 0) sh2[t >> 5] = s2;
    __syncthreads();
    float var = 0.f;
#pragma unroll
    for (int i = 0; i < 8; i++) var += sh2[i];
    var *= (1.f / 256.f);

    const float o = d * rsqrtf(var + 1e-5f) * g[t] + be[t];
    out[row * 256 + t] = o;
    if (out_r) out_r[row * 256 + t] = rtf(o);
}

// ---------------------------------------------------------------------------
// Launch
// ---------------------------------------------------------------------------
extern "C" void kernel_launch(void* const* d_in, const int* in_sizes, int n_in,
                              void* d_out, int out_size) {
    const float* src  = (const float*)d_in[0];
    const float* pos  = (const float*)d_in[1];
    const float* refp = (const float*)d_in[2];
    const int*   shp  = (const int*)d_in[3];
    const int*   lst  = (const int*)d_in[4];
    const float* Wv   = (const float*)d_in[5];
    const float* bv   = (const float*)d_in[6];
    const float* Woff = (const float*)d_in[7];
    const float* boff = (const float*)d_in[8];
    const float* Waw  = (const float*)d_in[9];
    const float* baw  = (const float*)d_in[10];
    const float* Wo   = (const float*)d_in[11];
    const float* bo   = (const float*)d_in[12];
    const float* W1   = (const float*)d_in[13];
    const float* b1   = (const float*)d_in[14];
    const float* W2   = (const float*)d_in[15];
    const float* b2   = (const float*)d_in[16];
    const float* g1   = (const float*)d_in[17];
    const float* be1  = (const float*)d_in[18];
    const float* g2   = (const float*)d_in[19];
    const float* be2  = (const float*)d_in[20];

    const int M = in_sizes[0] / CDIM;   // 43520
    const int Lq = 21760;
    float* out = (float*)d_out;

    float *q, *srcr, *val, *off, *aw, *attn, *x, *xr, *hid, *f, *wt;
    cudaGetSymbolAddress((void**)&q,    g_q);
    cudaGetSymbolAddress((void**)&srcr, g_srcr);
    cudaGetSymbolAddress((void**)&val,  g_val);
    cudaGetSymbolAddress((void**)&off,  g_off);
    cudaGetSymbolAddress((void**)&aw,   g_aw);
    cudaGetSymbolAddress((void**)&attn, g_attn);
    cudaGetSymbolAddress((void**)&x,    g_x);
    cudaGetSymbolAddress((void**)&xr,   g_xr);
    cudaGetSymbolAddress((void**)&hid,  g_hid);
    cudaGetSymbolAddress((void**)&f,    g_f);
    cudaGetSymbolAddress((void**)&wt,   g_wt);

    cudaFuncSetAttribute(gemm_mma_kernel<false, false>,
                         cudaFuncAttributeMaxDynamicSharedMemorySize, GSMEM_BYTES);
    cudaFuncSetAttribute(gemm_mma_kernel<true, true>,
                         cudaFuncAttributeMaxDynamicSharedMemorySize, GSMEM_BYTES);

    // transpose + round weights to [N][K]
    dim3 tb(32, 8);
    transpose_kernel<<<dim3(CDIM / 32, CDIM / 32), tb>>>(Wv,   wt + WT_WV,   CDIM, CDIM);
    transpose_kernel<<<dim3(CDIM / 32, CDIM / 32), tb>>>(Woff, wt + WT_WOFF, CDIM, CDIM);
    transpose_kernel<<<dim3(128 / 32,  CDIM / 32), tb>>>(Waw,  wt + WT_WAW,  CDIM, 128);
    transpose_kernel<<<dim3(CDIM / 32, CDIM / 32), tb>>>(Wo,   wt + WT_WO,   CDIM, CDIM);
    transpose_kernel<<<dim3(FDIM / 32, CDIM / 32), tb>>>(W1,   wt + WT_W1,   CDIM, FDIM);
    transpose_kernel<<<dim3(CDIM / 32, FDIM / 32), tb>>>(W2,   wt + WT_W2,   FDIM, CDIM);

    const int nElem = M * CDIM;
    addq_kernel<<<(nElem + 255) / 256, 256>>>(src, pos, q, srcr, nElem);

    dim3 blk(128);
    gemm_mma_kernel<false, false><<<dim3(CDIM / 128, M / 128), blk, GSMEM_BYTES>>>(srcr, wt + WT_WV,   bv,   val, M, CDIM, CDIM);
    gemm_mma_kernel<false, false><<<dim3(CDIM / 128, M / 128), blk, GSMEM_BYTES>>>(q,    wt + WT_WOFF, boff, off, M, CDIM, CDIM);
    gemm_mma_kernel<false, false><<<dim3(1,          M / 128), blk, GSMEM_BYTES>>>(q,    wt + WT_WAW,  baw,  aw,  M, 128,  CDIM);
    sample_kernel<<<M, 256>>>(val, off, aw, refp, shp, lst, attn, Lq);
    gemm_mma_kernel<false, false><<<dim3(CDIM / 128, M / 128), blk, GSMEM_BYTES>>>(attn, wt + WT_WO, bo, f, M, CDIM, CDIM);
    ln_kernel<<<M, 256>>>(src, f, g1, be1, x, xr);
    gemm_mma_kernel<true, true><<<dim3(FDIM / 128, M / 128), blk, GSMEM_BYTES>>>(xr,  wt + WT_W1, b1, hid, M, FDIM, CDIM);
    gemm_mma_kernel<false, false><<<dim3(CDIM / 128, M / 128), blk, GSMEM_BYTES>>>(hid, wt + WT_W2, b2, f,  M, CDIM, FDIM);
    ln_kernel<<<M, 256>>>(x, f, g2, be2, out, nullptr);
}